// round 2
// baseline (speedup 1.0000x reference)
#include <cuda_runtime.h>
#include <math.h>

#define N_TOK  32768
#define DDIM   256
#define KCODE  1024
#define HW_    1024
#define BATCH  32

// ---- scratch (no allocations allowed) ----
__device__ float  g_eNorm[KCODE];
__device__ float  g_znorm[N_TOK];
__device__ float  g_sumE[DDIM];
__device__ float  g_sumZ[DDIM];
__device__ int    g_counts[KCODE];
__device__ int    g_idx[N_TOK];
__device__ double g_loss_acc;
__device__ double g_zsq_acc;
__device__ double g_e2_acc;

// ------------------------------------------------------------------
__global__ void k_zero() {
    int t = blockIdx.x * blockDim.x + threadIdx.x;
    if (t < KCODE) g_counts[t] = 0;
    if (t < DDIM)  { g_sumE[t] = 0.f; g_sumZ[t] = 0.f; }
    if (t == 0) { g_loss_acc = 0.0; g_zsq_acc = 0.0; g_e2_acc = 0.0; }
}

// per-code squared norm + total sum of norms
__global__ void k_enorm(const float* __restrict__ E) {
    int k = blockIdx.x;
    int t = threadIdx.x;                      // 64 threads, 4 floats each
    float4 v = ((const float4*)(E + (size_t)k * DDIM))[t];
    float s = v.x * v.x + v.y * v.y + v.z * v.z + v.w * v.w;
    #pragma unroll
    for (int o = 16; o; o >>= 1) s += __shfl_down_sync(0xffffffffu, s, o);
    __shared__ float ws[2];
    if ((t & 31) == 0) ws[t >> 5] = s;
    __syncthreads();
    if (t == 0) {
        float tot = ws[0] + ws[1];
        g_eNorm[k] = tot;
        atomicAdd(&g_e2_acc, (double)tot);
    }
}

// per-token squared norm (fp32, matching reference's binade/grid structure)
__global__ void k_znorm(const float* __restrict__ Z) {
    int t = blockIdx.x * 128 + threadIdx.x;   // 256 blocks x 128 threads
    int b = t >> 10;
    int hw = t & 1023;
    const float* p = Z + ((size_t)b << 18) + hw;   // b*256*1024
    float s = 0.f;
    #pragma unroll 8
    for (int d = 0; d < DDIM; d++) {
        float v = p[(size_t)d << 10];
        s += v * v;
    }
    g_znorm[t] = s;
}

// column sums of E (for mean_distance)
__global__ void k_sume(const float* __restrict__ E) {
    int d  = threadIdx.x;                     // 256 threads
    int k0 = blockIdx.x * 128;                // 8 blocks
    float s = 0.f;
    for (int k = k0; k < k0 + 128; k++) s += E[(size_t)k * DDIM + d];
    atomicAdd(&g_sumE[d], s);
}

// per-d sums of Z and total sum of z^2 (for mean_distance)
__global__ void k_sumz(const float* __restrict__ Z) {
    int d = blockIdx.x;                       // 256 blocks
    int tid = threadIdx.x;                    // 256 threads
    float  s = 0.f;
    double q = 0.0;
    for (int b = 0; b < BATCH; b++) {
        const float* p = Z + ((size_t)b * DDIM + d) * HW_;
        #pragma unroll
        for (int base = 0; base < HW_; base += 256) {
            float v = p[base + tid];
            s += v;
            q += (double)v * (double)v;
        }
    }
    __shared__ float  sf[256];
    __shared__ double sd[256];
    sf[tid] = s; sd[tid] = q;
    __syncthreads();
    for (int o = 128; o; o >>= 1) {
        if (tid < o) { sf[tid] += sf[tid + o]; sd[tid] += sd[tid + o]; }
        __syncthreads();
    }
    if (tid == 0) {
        g_sumZ[d] = sf[0];
        atomicAdd(&g_zsq_acc, sd[0]);
    }
}

// ------------------------------------------------------------------
// fused fp32 GEMM + argmin: block = 128 tokens x (all 1024 codes in 8 tiles)
// Score emulates the reference's eager fp32 op sequence:
//   d = fl( fl(zn + en_k) - 2*fl(dot) )   on the ulp(256) grid,
// argmin ties resolved by lowest code index (jnp.argmin semantics).
__global__ __launch_bounds__(256) void k_argmin(const float* __restrict__ Z,
                                                const float* __restrict__ E) {
    __shared__ float As[16][128];     // [d][token]
    __shared__ float Bs[16][128];     // [d][code]
    __shared__ float sEN[KCODE];
    __shared__ float szn[128];
    __shared__ float redV[128][16];
    __shared__ int   redI[128][16];

    int tid = threadIdx.x;
    int tb  = blockIdx.x;             // 0..255
    int b   = tb >> 3;
    int hw0 = (tb & 7) << 7;
    int tx  = tid & 15;
    int ty  = tid >> 4;

    for (int i = tid; i < KCODE; i += 256) sEN[i] = g_eNorm[i];
    if (tid < 128) szn[tid] = g_znorm[tb * 128 + tid];

    float best[8];
    int   bidx[8];
    #pragma unroll
    for (int i = 0; i < 8; i++) { best[i] = 3.4e38f; bidx[i] = 0; }

    const float* Zbase = Z + ((size_t)b * DDIM) * HW_ + hw0;

    for (int ct = 0; ct < 8; ct++) {
        float acc[8][8];
        #pragma unroll
        for (int i = 0; i < 8; i++)
            #pragma unroll
            for (int j = 0; j < 8; j++) acc[i][j] = 0.f;

        for (int dt = 0; dt < 16; dt++) {
            // load z tile: 16 d-rows x 128 tokens (coalesced float4)
            #pragma unroll
            for (int r2 = 0; r2 < 2; r2++) {
                int li   = tid + r2 * 256;          // 0..511 float4 slots
                int drow = li >> 5;                 // 32 float4 per row
                int tcol = (li & 31) << 2;
                float4 v = *(const float4*)(Zbase + (size_t)(dt * 16 + drow) * HW_ + tcol);
                *(float4*)&As[drow][tcol] = v;
            }
            // load e tile: 128 codes x 16 d (transpose into [d][code])
            #pragma unroll
            for (int r2 = 0; r2 < 2; r2++) {
                int li   = tid + r2 * 256;
                int code = li >> 2;                 // 0..127
                int dq   = (li & 3) << 2;           // 0,4,8,12
                float4 v = *(const float4*)(E + (size_t)(ct * 128 + code) * DDIM + dt * 16 + dq);
                Bs[dq + 0][code] = v.x;
                Bs[dq + 1][code] = v.y;
                Bs[dq + 2][code] = v.z;
                Bs[dq + 3][code] = v.w;
            }
            __syncthreads();

            #pragma unroll
            for (int kk = 0; kk < 16; kk++) {
                float a[8], bb[8];
                #pragma unroll
                for (int i = 0; i < 8; i++) a[i]  = As[kk][ty * 8 + i];
                #pragma unroll
                for (int j = 0; j < 8; j++) bb[j] = Bs[kk][tx * 8 + j];
                #pragma unroll
                for (int i = 0; i < 8; i++)
                    #pragma unroll
                    for (int j = 0; j < 8; j++) acc[i][j] += a[i] * bb[j];
            }
            __syncthreads();
        }

        // fold scores into running min, emulating reference rounding:
        //   t1 = fl(zn + en);  s = fl(t1 - 2*acc)   (2*acc is exact)
        // __fadd_rn blocks FMA contraction so each step rounds like jax eager.
        #pragma unroll
        for (int j = 0; j < 8; j++) {
            int   c  = ct * 128 + tx * 8 + j;
            float en = sEN[c];
            #pragma unroll
            for (int i = 0; i < 8; i++) {
                float t1 = __fadd_rn(szn[ty * 8 + i], en);
                float s  = __fadd_rn(t1, -2.0f * acc[i][j]);
                if (s < best[i]) { best[i] = s; bidx[i] = c; }
            }
        }
    }

    // cross-thread reduction over the 16 column-groups per token row
    #pragma unroll
    for (int i = 0; i < 8; i++) {
        redV[ty * 8 + i][tx] = best[i];
        redI[ty * 8 + i][tx] = bidx[i];
    }
    __syncthreads();
    if (tid < 128) {
        float bv = redV[tid][0];
        int   bi = redI[tid][0];
        #pragma unroll
        for (int t = 1; t < 16; t++) {
            float v  = redV[tid][t];
            int   ii = redI[tid][t];
            if (v < bv || (v == bv && ii < bi)) { bv = v; bi = ii; }
        }
        g_idx[tb * 128 + tid] = bi;
        atomicAdd(&g_counts[bi], 1);
    }
}

// ------------------------------------------------------------------
// gather codes -> out (NCHW), accumulate loss sum
__global__ __launch_bounds__(256) void k_out(const float* __restrict__ Z,
                                             const float* __restrict__ E,
                                             float* __restrict__ out) {
    __shared__ int sidx[128];
    int tid = threadIdx.x;
    int tb  = blockIdx.x;
    int b   = tb >> 3;
    int hw0 = (tb & 7) << 7;
    if (tid < 128) sidx[tid] = g_idx[tb * 128 + tid];
    __syncthreads();

    int t  = tid & 127;
    int dg = tid >> 7;
    int myidx = sidx[t];
    size_t zb = ((size_t)b * DDIM) * HW_ + hw0 + t;

    double lsum = 0.0;
    for (int d = dg; d < DDIM; d += 2) {
        float ov = E[(size_t)myidx * DDIM + d];
        float zv = Z[zb + (size_t)d * HW_];
        out[zb + (size_t)d * HW_] = ov;
        float df = ov - zv;
        lsum += (double)df * (double)df;
    }

    // block reduce double
    __shared__ double sred[256];
    sred[tid] = lsum;
    __syncthreads();
    for (int o = 128; o; o >>= 1) {
        if (tid < o) sred[tid] += sred[tid + o];
        __syncthreads();
    }
    if (tid == 0) atomicAdd(&g_loss_acc, sred[0]);
}

// ------------------------------------------------------------------
__global__ void k_final(float* __restrict__ tail) {
    __shared__ double shd[256];
    __shared__ double she[256];
    int tid = threadIdx.x;

    double dot = (tid < DDIM) ? (double)g_sumZ[tid] * (double)g_sumE[tid] : 0.0;
    double ent = 0.0;
    for (int k = tid; k < KCODE; k += 256) {
        double p = (double)g_counts[k] / (double)N_TOK;
        ent += p * log(p + 1e-10);
    }
    shd[tid] = dot; she[tid] = ent;
    __syncthreads();
    for (int o = 128; o; o >>= 1) {
        if (tid < o) { shd[tid] += shd[tid + o]; she[tid] += she[tid + o]; }
        __syncthreads();
    }
    if (tid == 0) {
        double md = g_zsq_acc / (double)N_TOK
                  + g_e2_acc  / (double)KCODE
                  - 2.0 * shd[0] / ((double)N_TOK * (double)KCODE);
        double loss = 1.25 * g_loss_acc / ((double)N_TOK * (double)DDIM);
        double perp = exp(-she[0]);
        tail[0] = (float)loss;
        tail[1] = (float)perp;
        tail[2] = (float)md;
    }
}

// ------------------------------------------------------------------
extern "C" void kernel_launch(void* const* d_in, const int* in_sizes, int n_in,
                              void* d_out, int out_size) {
    const float* Z = (const float*)d_in[0];   // [32,256,32,32]
    const float* E = (const float*)d_in[1];   // [1024,256]
    float* out = (float*)d_out;

    k_zero  <<<5, 256>>>();
    k_enorm <<<KCODE, 64>>>(E);
    k_znorm <<<256, 128>>>(Z);
    k_sume  <<<8, 256>>>(E);
    k_sumz  <<<DDIM, 256>>>(Z);
    k_argmin<<<256, 256>>>(Z, E);
    k_out   <<<256, 256>>>(Z, E, out);
    k_final <<<1, 256>>>(out + (out_size - 3));
}

// round 3
// speedup vs baseline: 1.0030x; 1.0030x over previous
#include <cuda_runtime.h>
#include <math.h>

#define N_TOK  32768
#define DDIM   256
#define KCODE  1024
#define HW_    1024
#define BATCH  32

// ---- scratch (no allocations allowed) ----
__device__ float  g_eNorm[KCODE];
__device__ float  g_znorm[N_TOK];
__device__ float  g_sumE[DDIM];
__device__ float  g_sumZ[DDIM];
__device__ int    g_counts[KCODE];
__device__ int    g_idx[N_TOK];
__device__ double g_loss_acc;
__device__ double g_zsq_acc;
__device__ double g_e2_acc;

// ------------------------------------------------------------------
__global__ void k_zero() {
    int t = blockIdx.x * blockDim.x + threadIdx.x;
    if (t < KCODE) g_counts[t] = 0;
    if (t < DDIM)  { g_sumE[t] = 0.f; g_sumZ[t] = 0.f; }
    if (t == 0) { g_loss_acc = 0.0; g_zsq_acc = 0.0; g_e2_acc = 0.0; }
}

// per-code squared norm + total sum of norms
__global__ void k_enorm(const float* __restrict__ E) {
    int k = blockIdx.x;
    int t = threadIdx.x;                      // 64 threads, 4 floats each
    float4 v = ((const float4*)(E + (size_t)k * DDIM))[t];
    float s = v.x * v.x + v.y * v.y + v.z * v.z + v.w * v.w;
    #pragma unroll
    for (int o = 16; o; o >>= 1) s += __shfl_down_sync(0xffffffffu, s, o);
    __shared__ float ws[2];
    if ((t & 31) == 0) ws[t >> 5] = s;
    __syncthreads();
    if (t == 0) {
        float tot = ws[0] + ws[1];
        g_eNorm[k] = tot;
        atomicAdd(&g_e2_acc, (double)tot);
    }
}

// per-token squared norm (fp32, matching reference's binade/grid structure)
__global__ void k_znorm(const float* __restrict__ Z) {
    int t = blockIdx.x * 128 + threadIdx.x;   // 256 blocks x 128 threads
    int b = t >> 10;
    int hw = t & 1023;
    const float* p = Z + ((size_t)b << 18) + hw;   // b*256*1024
    float s = 0.f;
    #pragma unroll 8
    for (int d = 0; d < DDIM; d++) {
        float v = p[(size_t)d << 10];
        s += v * v;
    }
    g_znorm[t] = s;
}

// column sums of E (for mean_distance)
__global__ void k_sume(const float* __restrict__ E) {
    int d  = threadIdx.x;                     // 256 threads
    int k0 = blockIdx.x * 128;                // 8 blocks
    float s = 0.f;
    for (int k = k0; k < k0 + 128; k++) s += E[(size_t)k * DDIM + d];
    atomicAdd(&g_sumE[d], s);
}

// per-d sums of Z and total sum of z^2 (for mean_distance)
__global__ void k_sumz(const float* __restrict__ Z) {
    int d = blockIdx.x;                       // 256 blocks
    int tid = threadIdx.x;                    // 256 threads
    float  s = 0.f;
    double q = 0.0;
    for (int b = 0; b < BATCH; b++) {
        const float* p = Z + ((size_t)b * DDIM + d) * HW_;
        #pragma unroll
        for (int base = 0; base < HW_; base += 256) {
            float v = p[base + tid];
            s += v;
            q += (double)v * (double)v;
        }
    }
    __shared__ float  sf[256];
    __shared__ double sd[256];
    sf[tid] = s; sd[tid] = q;
    __syncthreads();
    for (int o = 128; o; o >>= 1) {
        if (tid < o) { sf[tid] += sf[tid + o]; sd[tid] += sd[tid + o]; }
        __syncthreads();
    }
    if (tid == 0) {
        g_sumZ[d] = sf[0];
        atomicAdd(&g_zsq_acc, sd[0]);
    }
}

// ------------------------------------------------------------------
// fused fp32 GEMM + argmin: block = 128 tokens x (all 1024 codes in 8 tiles)
// Score emulates the reference's eager fp32 op sequence:
//   d = fl( fl(zn + en_k) - 2*fl(dot) )   on the ulp(256) grid,
// argmin ties resolved by lowest code index (jnp.argmin semantics).
__global__ __launch_bounds__(256) void k_argmin(const float* __restrict__ Z,
                                                const float* __restrict__ E) {
    __shared__ float As[16][128];     // [d][token]
    __shared__ float Bs[16][128];     // [d][code]
    __shared__ float sEN[KCODE];
    __shared__ float szn[128];
    __shared__ float redV[128][16];
    __shared__ int   redI[128][16];

    int tid = threadIdx.x;
    int tb  = blockIdx.x;             // 0..255
    int b   = tb >> 3;
    int hw0 = (tb & 7) << 7;
    int tx  = tid & 15;
    int ty  = tid >> 4;

    for (int i = tid; i < KCODE; i += 256) sEN[i] = g_eNorm[i];
    if (tid < 128) szn[tid] = g_znorm[tb * 128 + tid];

    float best[8];
    int   bidx[8];
    #pragma unroll
    for (int i = 0; i < 8; i++) { best[i] = 3.4e38f; bidx[i] = 0; }

    const float* Zbase = Z + ((size_t)b * DDIM) * HW_ + hw0;

    for (int ct = 0; ct < 8; ct++) {
        float acc[8][8];
        #pragma unroll
        for (int i = 0; i < 8; i++)
            #pragma unroll
            for (int j = 0; j < 8; j++) acc[i][j] = 0.f;

        for (int dt = 0; dt < 16; dt++) {
            // load z tile: 16 d-rows x 128 tokens (coalesced float4)
            #pragma unroll
            for (int r2 = 0; r2 < 2; r2++) {
                int li   = tid + r2 * 256;          // 0..511 float4 slots
                int drow = li >> 5;                 // 32 float4 per row
                int tcol = (li & 31) << 2;
                float4 v = *(const float4*)(Zbase + (size_t)(dt * 16 + drow) * HW_ + tcol);
                *(float4*)&As[drow][tcol] = v;
            }
            // load e tile: 128 codes x 16 d (transpose into [d][code])
            #pragma unroll
            for (int r2 = 0; r2 < 2; r2++) {
                int li   = tid + r2 * 256;
                int code = li >> 2;                 // 0..127
                int dq   = (li & 3) << 2;           // 0,4,8,12
                float4 v = *(const float4*)(E + (size_t)(ct * 128 + code) * DDIM + dt * 16 + dq);
                Bs[dq + 0][code] = v.x;
                Bs[dq + 1][code] = v.y;
                Bs[dq + 2][code] = v.z;
                Bs[dq + 3][code] = v.w;
            }
            __syncthreads();

            #pragma unroll
            for (int kk = 0; kk < 16; kk++) {
                float a[8], bb[8];
                #pragma unroll
                for (int i = 0; i < 8; i++) a[i]  = As[kk][ty * 8 + i];
                #pragma unroll
                for (int j = 0; j < 8; j++) bb[j] = Bs[kk][tx * 8 + j];
                #pragma unroll
                for (int i = 0; i < 8; i++)
                    #pragma unroll
                    for (int j = 0; j < 8; j++) acc[i][j] += a[i] * bb[j];
            }
            __syncthreads();
        }

        // fold scores into running min, emulating reference rounding:
        //   t1 = fl(zn + en);  s = fl(t1 - 2*acc)   (2*acc is exact)
        // __fadd_rn blocks FMA contraction so each step rounds like jax eager.
        #pragma unroll
        for (int j = 0; j < 8; j++) {
            int   c  = ct * 128 + tx * 8 + j;
            float en = sEN[c];
            #pragma unroll
            for (int i = 0; i < 8; i++) {
                float t1 = __fadd_rn(szn[ty * 8 + i], en);
                float s  = __fadd_rn(t1, -2.0f * acc[i][j]);
                if (s < best[i]) { best[i] = s; bidx[i] = c; }
            }
        }
    }

    // cross-thread reduction over the 16 column-groups per token row
    #pragma unroll
    for (int i = 0; i < 8; i++) {
        redV[ty * 8 + i][tx] = best[i];
        redI[ty * 8 + i][tx] = bidx[i];
    }
    __syncthreads();
    if (tid < 128) {
        float bv = redV[tid][0];
        int   bi = redI[tid][0];
        #pragma unroll
        for (int t = 1; t < 16; t++) {
            float v  = redV[tid][t];
            int   ii = redI[tid][t];
            if (v < bv || (v == bv && ii < bi)) { bv = v; bi = ii; }
        }
        g_idx[tb * 128 + tid] = bi;
        atomicAdd(&g_counts[bi], 1);
    }
}

// ------------------------------------------------------------------
// gather codes -> out (NCHW), accumulate loss sum
__global__ __launch_bounds__(256) void k_out(const float* __restrict__ Z,
                                             const float* __restrict__ E,
                                             float* __restrict__ out) {
    __shared__ int sidx[128];
    int tid = threadIdx.x;
    int tb  = blockIdx.x;
    int b   = tb >> 3;
    int hw0 = (tb & 7) << 7;
    if (tid < 128) sidx[tid] = g_idx[tb * 128 + tid];
    __syncthreads();

    int t  = tid & 127;
    int dg = tid >> 7;
    int myidx = sidx[t];
    size_t zb = ((size_t)b * DDIM) * HW_ + hw0 + t;

    double lsum = 0.0;
    for (int d = dg; d < DDIM; d += 2) {
        float ov = E[(size_t)myidx * DDIM + d];
        float zv = Z[zb + (size_t)d * HW_];
        out[zb + (size_t)d * HW_] = ov;
        float df = ov - zv;
        lsum += (double)df * (double)df;
    }

    // block reduce double
    __shared__ double sred[256];
    sred[tid] = lsum;
    __syncthreads();
    for (int o = 128; o; o >>= 1) {
        if (tid < o) sred[tid] += sred[tid + o];
        __syncthreads();
    }
    if (tid == 0) atomicAdd(&g_loss_acc, sred[0]);
}

// ------------------------------------------------------------------
__global__ void k_final(float* __restrict__ tail) {
    __shared__ double shd[256];
    __shared__ double she[256];
    int tid = threadIdx.x;

    double dot = (tid < DDIM) ? (double)g_sumZ[tid] * (double)g_sumE[tid] : 0.0;
    double ent = 0.0;
    for (int k = tid; k < KCODE; k += 256) {
        double p = (double)g_counts[k] / (double)N_TOK;
        ent += p * log(p + 1e-10);
    }
    shd[tid] = dot; she[tid] = ent;
    __syncthreads();
    for (int o = 128; o; o >>= 1) {
        if (tid < o) { shd[tid] += shd[tid + o]; she[tid] += she[tid + o]; }
        __syncthreads();
    }
    if (tid == 0) {
        double md = g_zsq_acc / (double)N_TOK
                  + g_e2_acc  / (double)KCODE
                  - 2.0 * shd[0] / ((double)N_TOK * (double)KCODE);
        double loss = 1.25 * g_loss_acc / ((double)N_TOK * (double)DDIM);
        double perp = exp(-she[0]);
        tail[0] = (float)loss;
        tail[1] = (float)perp;
        tail[2] = (float)md;
    }
}

// ------------------------------------------------------------------
extern "C" void kernel_launch(void* const* d_in, const int* in_sizes, int n_in,
                              void* d_out, int out_size) {
    const float* Z = (const float*)d_in[0];   // [32,256,32,32]
    const float* E = (const float*)d_in[1];   // [1024,256]
    float* out = (float*)d_out;

    k_zero  <<<5, 256>>>();
    k_enorm <<<KCODE, 64>>>(E);
    k_znorm <<<256, 128>>>(Z);
    k_sume  <<<8, 256>>>(E);
    k_sumz  <<<DDIM, 256>>>(Z);
    k_argmin<<<256, 256>>>(Z, E);
    k_out   <<<256, 256>>>(Z, E, out);
    k_final <<<1, 256>>>(out + (out_size - 3));
}

// round 6
// speedup vs baseline: 2.2110x; 2.2043x over previous
#include <cuda_runtime.h>
#include <cuda_bf16.h>
#include <math.h>
#include <stdint.h>

#define N_TOK  32768
#define DDIM   256
#define KCODE  1024
#define HW_    1024
#define BATCH  32
#define MARGIN 2.0e-3f

// ---- scratch (static device globals; no allocations allowed) ----
__device__ float  g_eNorm[KCODE];
__device__ float  g_znorm[N_TOK];
__device__ float  g_sumE[DDIM];
__device__ float  g_sumZ[DDIM];
__device__ int    g_counts[KCODE];
__device__ int    g_idx[N_TOK];
__device__ double g_loss_acc;
__device__ double g_zsq_acc;
__device__ double g_e2_acc;

__device__ __nv_bfloat16 g_Zb[(size_t)N_TOK * DDIM];    // 16MB  token-major bf16
__device__ float         g_Zt[(size_t)N_TOK * DDIM];    // 32MB  token-major fp32
__device__ __nv_bfloat16 g_Eb[(size_t)KCODE * DDIM];    // 512KB
__device__ __nv_bfloat16 g_stil[(size_t)N_TOK * KCODE]; // 64MB  approx scores

// ------------------------------------------------------------------
__global__ void k_zero() {
    int t = blockIdx.x * blockDim.x + threadIdx.x;
    if (t < KCODE) g_counts[t] = 0;
    if (t < DDIM)  { g_sumE[t] = 0.f; g_sumZ[t] = 0.f; }
    if (t == 0) { g_loss_acc = 0.0; g_zsq_acc = 0.0; g_e2_acc = 0.0; }
}

// per-code squared norm + total sum of norms
__global__ void k_enorm(const float* __restrict__ E) {
    int k = blockIdx.x;
    int t = threadIdx.x;                      // 64 threads, 4 floats each
    float4 v = ((const float4*)(E + (size_t)k * DDIM))[t];
    float s = v.x * v.x + v.y * v.y + v.z * v.z + v.w * v.w;
    #pragma unroll
    for (int o = 16; o; o >>= 1) s += __shfl_down_sync(0xffffffffu, s, o);
    __shared__ float ws[2];
    if ((t & 31) == 0) ws[t >> 5] = s;
    __syncthreads();
    if (t == 0) {
        float tot = ws[0] + ws[1];
        g_eNorm[k] = tot;
        atomicAdd(&g_e2_acc, (double)tot);
    }
}

// per-token squared norm (fp32; any fp32 order is argmin-equivalent)
__global__ void k_znorm(const float* __restrict__ Z) {
    int t = blockIdx.x * 128 + threadIdx.x;
    int b = t >> 10;
    int hw = t & 1023;
    const float* p = Z + ((size_t)b << 18) + hw;
    float s = 0.f;
    #pragma unroll 8
    for (int d = 0; d < DDIM; d++) {
        float v = p[(size_t)d << 10];
        s += v * v;
    }
    g_znorm[t] = s;
}

// column sums of E (for mean_distance)
__global__ void k_sume(const float* __restrict__ E) {
    int d  = threadIdx.x;
    int k0 = blockIdx.x * 128;
    float s = 0.f;
    for (int k = k0; k < k0 + 128; k++) s += E[(size_t)k * DDIM + d];
    atomicAdd(&g_sumE[d], s);
}

// per-d sums of Z and total sum of z^2 (for mean_distance)
__global__ void k_sumz(const float* __restrict__ Z) {
    int d = blockIdx.x;
    int tid = threadIdx.x;
    float  s = 0.f;
    double q = 0.0;
    for (int b = 0; b < BATCH; b++) {
        const float* p = Z + ((size_t)b * DDIM + d) * HW_;
        #pragma unroll
        for (int base = 0; base < HW_; base += 256) {
            float v = p[base + tid];
            s += v;
            q += (double)v * (double)v;
        }
    }
    __shared__ float  sf[256];
    __shared__ double sd[256];
    sf[tid] = s; sd[tid] = q;
    __syncthreads();
    for (int o = 128; o; o >>= 1) {
        if (tid < o) { sf[tid] += sf[tid + o]; sd[tid] += sd[tid + o]; }
        __syncthreads();
    }
    if (tid == 0) {
        g_sumZ[d] = sf[0];
        atomicAdd(&g_zsq_acc, sd[0]);
    }
}

// ------------------------------------------------------------------
// transpose Z [b,d,hw] -> token-major Zt (fp32) and Zb (bf16)
__global__ __launch_bounds__(256) void k_prep(const float* __restrict__ Z) {
    __shared__ float tile[256][33];
    int tid = threadIdx.x;
    int b   = blockIdx.x >> 5;
    int hw0 = (blockIdx.x & 31) << 5;
    int lane = tid & 31, dg = tid >> 5;     // dg 0..7
    #pragma unroll
    for (int i = 0; i < 32; i++) {
        int d = dg * 32 + i;
        tile[d][lane] = Z[(((size_t)b * DDIM + d) << 10) + hw0 + lane];
    }
    __syncthreads();
    int h = tid & 31, ds = tid >> 5;        // ds 0..7 (d segment of 32)
    size_t tk = (size_t)b * 1024 + hw0 + h;
    float buf[32];
    #pragma unroll
    for (int i = 0; i < 32; i++) buf[i] = tile[ds * 32 + i][h];
    #pragma unroll
    for (int q = 0; q < 8; q++)
        *(float4*)&g_Zt[tk * DDIM + ds * 32 + q * 4] =
            make_float4(buf[q*4], buf[q*4+1], buf[q*4+2], buf[q*4+3]);
    #pragma unroll
    for (int q = 0; q < 4; q++) {
        union { uint4 u; __nv_bfloat162 h2[4]; } pk;
        #pragma unroll
        for (int j = 0; j < 4; j++)
            pk.h2[j] = __floats2bfloat162_rn(buf[q*8 + j*2], buf[q*8 + j*2 + 1]);
        *(uint4*)&g_Zb[tk * DDIM + ds * 32 + q * 8] = pk.u;
    }
}

// E fp32 -> bf16
__global__ void k_e2bf(const float* __restrict__ E) {
    int idx = blockIdx.x * 256 + threadIdx.x;         // 32768 threads x 8 elems
    const float4* p = (const float4*)(E + (size_t)idx * 8);
    float4 a = p[0], b = p[1];
    union { uint4 u; __nv_bfloat162 h2[4]; } pk;
    pk.h2[0] = __floats2bfloat162_rn(a.x, a.y);
    pk.h2[1] = __floats2bfloat162_rn(a.z, a.w);
    pk.h2[2] = __floats2bfloat162_rn(b.x, b.y);
    pk.h2[3] = __floats2bfloat162_rn(b.z, b.w);
    *(uint4*)&g_Eb[(size_t)idx * 8] = pk.u;
}

// ------------------------------------------------------------------
__device__ __forceinline__ void mma_bf16(float* c, const uint32_t* a, const uint32_t* b) {
    asm volatile(
        "mma.sync.aligned.m16n8k16.row.col.f32.bf16.bf16.f32 "
        "{%0,%1,%2,%3}, {%4,%5,%6,%7}, {%8,%9}, {%0,%1,%2,%3};\n"
        : "+f"(c[0]), "+f"(c[1]), "+f"(c[2]), "+f"(c[3])
        : "r"(a[0]), "r"(a[1]), "r"(a[2]), "r"(a[3]), "r"(b[0]), "r"(b[1]));
}

// approx score GEMM: s~(t,k) = en[k] - 2 * dot_bf16(z_t, e_k), stored bf16.
// CTA: 256 tokens x full K loop, code chunks of 64. 512 threads = 16 warps,
// warp tile 32 tokens x 32 codes (2 m-frags x 4 n-frags of m16n8k16).
// smem rows padded to 264 bf16 (132 u32, 132 % 32 == 4) => conflict-free frags.
#define SMEM_MMA_BYTES ((256 * 132 + 64 * 132) * 4)
__global__ __launch_bounds__(512) void k_mma() {
    extern __shared__ uint32_t sm[];
    uint32_t* As = sm;                 // [256][132] u32 (= 264 bf16/row)
    uint32_t* Bs = sm + 256 * 132;     // [64][132]
    int tid = threadIdx.x;
    int tb  = blockIdx.x;              // 0..127, 256 tokens each

    // load A tile (256 tokens x 256 d bf16)
    #pragma unroll
    for (int i = 0; i < 16; i++) {
        int c = tid + 512 * i;         // 8192 chunks of 16B
        int row = c >> 5, col = c & 31;
        uint4 v = *(const uint4*)(g_Zb + ((size_t)(tb * 256 + row)) * DDIM + col * 8);
        *(uint4*)(As + row * 132 + col * 4) = v;
    }

    int w = tid >> 5, l = tid & 31;
    int m0 = (w & 7) * 32, n0 = (w >> 3) * 32;
    int l4 = l >> 2, lm = l & 3;

    float acc[2][4][4];
    #pragma unroll
    for (int mf = 0; mf < 2; mf++)
        #pragma unroll
        for (int nf = 0; nf < 4; nf++)
            #pragma unroll
            for (int q = 0; q < 4; q++) acc[mf][nf][q] = 0.f;

    for (int ch = 0; ch < 16; ch++) {
        __syncthreads();
        #pragma unroll
        for (int i = 0; i < 4; i++) {
            int c = tid + 512 * i;     // 2048 chunks: 64 rows x 32
            int row = c >> 5, col = c & 31;
            uint4 v = *(const uint4*)(g_Eb + ((size_t)(ch * 64 + row)) * DDIM + col * 8);
            *(uint4*)(Bs + row * 132 + col * 4) = v;
        }
        __syncthreads();

        #pragma unroll
        for (int ks = 0; ks < 16; ks++) {
            int ka = ks * 8 + lm;
            uint32_t a[2][4], b[4][2];
            #pragma unroll
            for (int mf = 0; mf < 2; mf++) {
                int r = m0 + mf * 16 + l4;
                a[mf][0] = As[r * 132 + ka];
                a[mf][1] = As[(r + 8) * 132 + ka];
                a[mf][2] = As[r * 132 + ka + 4];
                a[mf][3] = As[(r + 8) * 132 + ka + 4];
            }
            #pragma unroll
            for (int nf = 0; nf < 4; nf++) {
                int n = n0 + nf * 8 + l4;
                b[nf][0] = Bs[n * 132 + ka];
                b[nf][1] = Bs[n * 132 + ka + 4];
            }
            #pragma unroll
            for (int mf = 0; mf < 2; mf++)
                #pragma unroll
                for (int nf = 0; nf < 4; nf++)
                    mma_bf16(acc[mf][nf], a[mf], b[nf]);
        }

        // epilogue: s~ = en - 2*dot -> bf16 store; reset acc
        #pragma unroll
        for (int mf = 0; mf < 2; mf++) {
            size_t t0 = (size_t)tb * 256 + m0 + mf * 16 + l4;
            #pragma unroll
            for (int nf = 0; nf < 4; nf++) {
                int cg = ch * 64 + n0 + nf * 8 + lm * 2;
                float2 en = *(const float2*)&g_eNorm[cg];
                float s00 = en.x - 2.f * acc[mf][nf][0];
                float s01 = en.y - 2.f * acc[mf][nf][1];
                float s10 = en.x - 2.f * acc[mf][nf][2];
                float s11 = en.y - 2.f * acc[mf][nf][3];
                *(__nv_bfloat162*)&g_stil[t0 * KCODE + cg] =
                    __floats2bfloat162_rn(s00, s01);
                *(__nv_bfloat162*)&g_stil[(t0 + 8) * KCODE + cg] =
                    __floats2bfloat162_rn(s10, s11);
                acc[mf][nf][0] = 0.f; acc[mf][nf][1] = 0.f;
                acc[mf][nf][2] = 0.f; acc[mf][nf][3] = 0.f;
            }
        }
    }
}

// ------------------------------------------------------------------
// exact rescore: warp per token. min over approx row, exact fp32 score for
// candidates within MARGIN, reference rounding emulation + low-index ties.
__global__ __launch_bounds__(256) void k_rescore(const float* __restrict__ E) {
    int t = blockIdx.x * 8 + (threadIdx.x >> 5);
    int l = threadIdx.x & 31;

    float zr[8];
    *(float4*)&zr[0] = *(const float4*)&g_Zt[(size_t)t * DDIM + l * 8];
    *(float4*)&zr[4] = *(const float4*)&g_Zt[(size_t)t * DDIM + l * 8 + 4];
    float szn = g_znorm[t];

    // lane covers codes l*32 .. l*32+31
    float v[32];
    const uint4* sp = (const uint4*)(g_stil + (size_t)t * KCODE + l * 32);
    #pragma unroll
    for (int q = 0; q < 4; q++) {
        uint4 u = sp[q];
        uint32_t wd[4] = {u.x, u.y, u.z, u.w};
        #pragma unroll
        for (int j = 0; j < 4; j++) {
            float2 f = __bfloat1622float2(*(__nv_bfloat162*)&wd[j]);
            v[q * 8 + j * 2]     = f.x;
            v[q * 8 + j * 2 + 1] = f.y;
        }
    }
    float mn = v[0];
    #pragma unroll
    for (int i = 1; i < 32; i++) mn = fminf(mn, v[i]);
    #pragma unroll
    for (int o = 16; o; o >>= 1) mn = fminf(mn, __shfl_xor_sync(0xffffffffu, mn, o));
    float thr = mn + MARGIN;

    unsigned mask = 0;
    #pragma unroll
    for (int i = 0; i < 32; i++) if (v[i] <= thr) mask |= (1u << i);

    float best = 3.4e38f;
    int   bidx = 0;
    for (int L = 0; L < 32; L++) {
        unsigned m = __shfl_sync(0xffffffffu, mask, L);
        while (m) {
            int i = __ffs(m) - 1; m &= m - 1;
            int code = L * 32 + i;
            const float* e = E + (size_t)code * DDIM + l * 8;
            float4 e0 = *(const float4*)e;
            float4 e1 = *(const float4*)(e + 4);
            float p = zr[0] * e0.x;
            p = fmaf(zr[1], e0.y, p);
            p = fmaf(zr[2], e0.z, p);
            p = fmaf(zr[3], e0.w, p);
            p = fmaf(zr[4], e1.x, p);
            p = fmaf(zr[5], e1.y, p);
            p = fmaf(zr[6], e1.z, p);
            p = fmaf(zr[7], e1.w, p);
            #pragma unroll
            for (int o = 16; o; o >>= 1) p += __shfl_xor_sync(0xffffffffu, p, o);
            float t1 = __fadd_rn(szn, g_eNorm[code]);
            float s  = __fadd_rn(t1, -2.0f * p);
            if (s < best) { best = s; bidx = code; }
        }
    }
    if (l == 0) {
        g_idx[t] = bidx;
        atomicAdd(&g_counts[bidx], 1);
    }
}

// ------------------------------------------------------------------
// gather codes -> out (NCHW), accumulate loss sum
__global__ __launch_bounds__(256) void k_out(const float* __restrict__ Z,
                                             const float* __restrict__ E,
                                             float* __restrict__ out) {
    __shared__ int sidx[128];
    int tid = threadIdx.x;
    int tb  = blockIdx.x;
    int b   = tb >> 3;
    int hw0 = (tb & 7) << 7;
    if (tid < 128) sidx[tid] = g_idx[tb * 128 + tid];
    __syncthreads();

    int t  = tid & 127;
    int dg = tid >> 7;
    int myidx = sidx[t];
    size_t zb = ((size_t)b * DDIM) * HW_ + hw0 + t;

    double lsum = 0.0;
    for (int d = dg; d < DDIM; d += 2) {
        float ov = E[(size_t)myidx * DDIM + d];
        float zv = Z[zb + (size_t)d * HW_];
        out[zb + (size_t)d * HW_] = ov;
        float df = ov - zv;
        lsum += (double)df * (double)df;
    }

    __shared__ double sred[256];
    sred[tid] = lsum;
    __syncthreads();
    for (int o = 128; o; o >>= 1) {
        if (tid < o) sred[tid] += sred[tid + o];
        __syncthreads();
    }
    if (tid == 0) atomicAdd(&g_loss_acc, sred[0]);
}

// ------------------------------------------------------------------
__global__ void k_final(float* __restrict__ tail) {
    __shared__ double shd[256];
    __shared__ double she[256];
    int tid = threadIdx.x;

    double dot = (tid < DDIM) ? (double)g_sumZ[tid] * (double)g_sumE[tid] : 0.0;
    double ent = 0.0;
    for (int k = tid; k < KCODE; k += 256) {
        double p = (double)g_counts[k] / (double)N_TOK;
        ent += p * log(p + 1e-10);
    }
    shd[tid] = dot; she[tid] = ent;
    __syncthreads();
    for (int o = 128; o; o >>= 1) {
        if (tid < o) { shd[tid] += shd[tid + o]; she[tid] += she[tid + o]; }
        __syncthreads();
    }
    if (tid == 0) {
        double md = g_zsq_acc / (double)N_TOK
                  + g_e2_acc  / (double)KCODE
                  - 2.0 * shd[0] / ((double)N_TOK * (double)KCODE);
        double loss = 1.25 * g_loss_acc / ((double)N_TOK * (double)DDIM);
        double perp = exp(-she[0]);
        tail[0] = (float)loss;
        tail[1] = (float)perp;
        tail[2] = (float)md;
    }
}

// ------------------------------------------------------------------
extern "C" void kernel_launch(void* const* d_in, const int* in_sizes, int n_in,
                              void* d_out, int out_size) {
    const float* Z = (const float*)d_in[0];   // [32,256,32,32]
    const float* E = (const float*)d_in[1];   // [1024,256]
    float* out = (float*)d_out;

    cudaFuncSetAttribute(k_mma, cudaFuncAttributeMaxDynamicSharedMemorySize,
                         SMEM_MMA_BYTES);

    k_zero   <<<5, 256>>>();
    k_enorm  <<<KCODE, 64>>>(E);
    k_znorm  <<<256, 128>>>(Z);
    k_sume   <<<8, 256>>>(E);
    k_sumz   <<<DDIM, 256>>>(Z);
    k_prep   <<<1024, 256>>>(Z);
    k_e2bf   <<<128, 256>>>(E);
    k_mma    <<<128, 512, SMEM_MMA_BYTES>>>();
    k_rescore<<<4096, 256>>>(E);
    k_out    <<<256, 256>>>(Z, E, out);
    k_final  <<<1, 256>>>(out + (out_size - 3));
}